// round 9
// baseline (speedup 1.0000x reference)
#include <cuda_runtime.h>
#include <cstdint>
#include <math.h>

// Problem constants
constexpr int B = 2;
constexpr int H = 16;
constexpr int N = 2048;
constexpr int A = 128;           // head dim
constexpr int W = 2048;          // model width
constexpr int HD = H * A;        // 2048
constexpr int Mdim = B * N;      // 4096
constexpr int Kdim = W;          // 2048

// Scratch (device globals — no allocation allowed)
__device__ float g_qr [Mdim * Kdim];     // tf32-rounded q
__device__ float g_Wqr[HD * W];
__device__ float g_Wkr[HD * W];
__device__ float g_Wvr[HD * W];
__device__ float g_Wor[W * HD];
__device__ float g_Q  [B * H * N * A];   // head-major
__device__ float g_K  [B * H * N * A];
__device__ float g_V  [B * H * N * A];
__device__ float g_AO [Mdim * HD];       // [b*n, h*a], rna-rounded by attention

// ---------------------------------------------------------------------------
// helpers
// ---------------------------------------------------------------------------
__device__ __forceinline__ float rna_tf32(float x) {
    uint32_t u;
    asm("cvt.rna.tf32.f32 %0, %1;" : "=r"(u) : "f"(x));
    return __uint_as_float(u);
}
__device__ __forceinline__ uint32_t rna_tf32_bits(float x) {
    uint32_t u;
    asm("cvt.rna.tf32.f32 %0, %1;" : "=r"(u) : "f"(x));
    return u;
}
__device__ __forceinline__ float ex2f(float x) {
    float y;
    asm("ex2.approx.ftz.f32 %0, %1;" : "=f"(y) : "f"(x));
    return y;
}
__device__ __forceinline__ uint32_t smem_u32(const void* p) {
    uint32_t a;
    asm("{ .reg .u64 t; cvta.to.shared.u64 t, %1; cvt.u32.u64 %0, t; }"
        : "=r"(a) : "l"(p));
    return a;
}
__device__ __forceinline__ void mma_tf32(float* c, const uint32_t* a,
                                         uint32_t b0, uint32_t b1) {
    asm volatile(
        "mma.sync.aligned.m16n8k8.row.col.f32.tf32.tf32.f32 "
        "{%0,%1,%2,%3}, {%4,%5,%6,%7}, {%8,%9}, {%0,%1,%2,%3};"
        : "+f"(c[0]), "+f"(c[1]), "+f"(c[2]), "+f"(c[3])
        : "r"(a[0]), "r"(a[1]), "r"(a[2]), "r"(a[3]), "r"(b0), "r"(b1));
}
__device__ __forceinline__ void ldsm_x4(uint32_t* r, uint32_t addr) {
    asm volatile("ldmatrix.sync.aligned.m8n8.x4.shared.b16 {%0,%1,%2,%3}, [%4];"
                 : "=r"(r[0]), "=r"(r[1]), "=r"(r[2]), "=r"(r[3]) : "r"(addr));
}
#define CP_ASYNC4(dst, src) \
    asm volatile("cp.async.ca.shared.global [%0], [%1], 4;" :: "r"(dst), "l"(src))
#define CP_ASYNC16(dst, src) \
    asm volatile("cp.async.cg.shared.global [%0], [%1], 16;" :: "r"(dst), "l"(src))
#define CP_COMMIT() asm volatile("cp.async.commit_group;" ::: "memory")
#define CP_WAIT(n)  asm volatile("cp.async.wait_group %0;" :: "n"(n) : "memory")

// ---------------------------------------------------------------------------
// Fused rna-rounding pre-pass over q + 4 weights (single DRAM-bound launch).
// ---------------------------------------------------------------------------
constexpr int NQ4 = Mdim * Kdim / 4;   // 2,097,152
constexpr int NW4 = HD * W / 4;        // 1,048,576 = 2^20

__global__ void round_all_kernel(const float4* __restrict__ q,
                                 const float4* __restrict__ wq,
                                 const float4* __restrict__ wk,
                                 const float4* __restrict__ wv,
                                 const float4* __restrict__ wo,
                                 float4* __restrict__ qr,
                                 float4* __restrict__ wqr,
                                 float4* __restrict__ wkr,
                                 float4* __restrict__ wvr,
                                 float4* __restrict__ wor) {
    int i = blockIdx.x * blockDim.x + threadIdx.x;
    const float4* src;
    float4* dst;
    int off;
    if (i < NQ4) {
        src = q; dst = qr; off = i;
    } else {
        int j = i - NQ4;
        int w = j >> 20;
        off = j & (NW4 - 1);
        src = (w == 0) ? wq : (w == 1) ? wk : (w == 2) ? wv : wo;
        dst = (w == 0) ? wqr : (w == 1) ? wkr : (w == 2) ? wvr : wor;
    }
    float4 v = src[off];
    v.x = rna_tf32(v.x); v.y = rna_tf32(v.y);
    v.z = rna_tf32(v.z); v.w = rna_tf32(v.w);
    dst[off] = v;
}

// ---------------------------------------------------------------------------
// tf32 mma.sync GEMM v3: 128x128 CTA, BK=32, 128 threads, 4 warps of 64x64.
// 3-stage cp.async pipeline + register double-buffered fragments
// (ldsm for ks+1 issued before MMAs of ks).
// ---------------------------------------------------------------------------
constexpr int TILE_B     = 128 * 32 * 4;          // 16384 per operand
constexpr int STAGE_B    = 2 * TILE_B;            // 32768
constexpr int GEMM_SMEM  = 3 * STAGE_B;           // 98304

template <int SCATTER_C>
__device__ __forceinline__ void gemm_body(const float* __restrict__ Ag,
                                          const float* __restrict__ Bg,
                                          float* __restrict__ Cg) {
    extern __shared__ float gs[];
    const uint32_t sbase = smem_u32(gs);
    const int tid  = threadIdx.x;
    const int lane = tid & 31;
    const int wid  = tid >> 5;      // 0..3
    const int wm   = wid & 1;       // 64 rows each
    const int wn   = wid >> 1;      // 64 cols each
    const int m0   = blockIdx.y * 128;
    const int n0   = blockIdx.x * 128;

    float c[4][8][4];
#pragma unroll
    for (int mi = 0; mi < 4; mi++)
#pragma unroll
        for (int ni = 0; ni < 8; ni++)
#pragma unroll
            for (int j = 0; j < 4; j++) c[mi][ni][j] = 0.f;

    const int srow0 = tid >> 3;     // 0..15
    const int sc16  = tid & 7;
    auto stage = [&](int kt, int slot) {
        const uint32_t base = sbase + slot * STAGE_B;
        const float* Asrc = Ag + (size_t)(m0 + srow0) * Kdim + kt * 32 + sc16 * 4;
        const float* Bsrc = Bg + (size_t)(n0 + srow0) * Kdim + kt * 32 + sc16 * 4;
#pragma unroll
        for (int i = 0; i < 8; i++) {
            int row = srow0 + i * 16;
            uint32_t off = (uint32_t)row * 128 + ((sc16 ^ (row & 7)) << 4);
            CP_ASYNC16(base + off,          Asrc + (size_t)i * 16 * Kdim);
            CP_ASYNC16(base + TILE_B + off, Bsrc + (size_t)i * 16 * Kdim);
        }
    };

    const int a_row = wm * 64 + (lane & 15);
    const int a_hi  = lane >> 4;
    const int b_row = wn * 64 + (lane & 7) + ((lane >> 4) << 3);
    const int b_hi  = (lane >> 3) & 1;

    stage(0, 0); CP_COMMIT();
    stage(1, 1); CP_COMMIT();

    constexpr int NKT = Kdim / 32;
    int slot = 0;
    for (int kt = 0; kt < NKT; kt++) {
        CP_WAIT(1);
        __syncthreads();
        if (kt + 2 < NKT) {
            int ns = slot + 2; if (ns >= 3) ns -= 3;
            stage(kt + 2, ns);
        }
        CP_COMMIT();

        const uint32_t abase = sbase + slot * STAGE_B;
        const uint32_t bbase = abase + TILE_B;

        uint32_t af[2][4][4], bf[2][4][4];
        auto load_frags = [&](int buf, int ks) {
#pragma unroll
            for (int mi = 0; mi < 4; mi++) {
                int row = a_row + mi * 16;
                uint32_t addr = abase + (uint32_t)row * 128
                              + (((ks * 2 + a_hi) ^ (row & 7)) << 4);
                ldsm_x4(af[buf][mi], addr);
            }
#pragma unroll
            for (int nip = 0; nip < 4; nip++) {
                int row = b_row + nip * 16;
                uint32_t addr = bbase + (uint32_t)row * 128
                              + (((ks * 2 + b_hi) ^ (row & 7)) << 4);
                ldsm_x4(bf[buf][nip], addr);
            }
        };

        load_frags(0, 0);
#pragma unroll
        for (int ks = 0; ks < 4; ks++) {
            const int cur = ks & 1;
            if (ks < 3) load_frags(cur ^ 1, ks + 1);
#pragma unroll
            for (int nip = 0; nip < 4; nip++) {
#pragma unroll
                for (int mi = 0; mi < 4; mi++) {
                    mma_tf32(c[mi][2 * nip],     af[cur][mi],
                             bf[cur][nip][0], bf[cur][nip][1]);
                    mma_tf32(c[mi][2 * nip + 1], af[cur][mi],
                             bf[cur][nip][2], bf[cur][nip][3]);
                }
            }
        }
        slot++; if (slot >= 3) slot = 0;
    }

    const int gid = lane >> 2, tig = lane & 3;
#pragma unroll
    for (int mi = 0; mi < 4; mi++) {
#pragma unroll
        for (int ni = 0; ni < 8; ni++) {
            int n = n0 + wn * 64 + ni * 8 + tig * 2;
#pragma unroll
            for (int half = 0; half < 2; half++) {
                int m = m0 + wm * 64 + mi * 16 + gid + half * 8;
                float2 v = make_float2(c[mi][ni][half * 2], c[mi][ni][half * 2 + 1]);
                size_t dst;
                if (SCATTER_C) {
                    int b2 = m >> 11, np = m & 2047, h2 = n >> 7, a0 = n & 127;
                    dst = ((((size_t)b2 * H + h2) * N) + np) * A + a0;
                } else {
                    dst = (size_t)m * 2048 + n;
                }
                *(float2*)(Cg + dst) = v;
            }
        }
    }
}

__global__ __launch_bounds__(128, 2)
void qkv_gemm(const float* __restrict__ q,
              const float* __restrict__ Wq, const float* __restrict__ Wk,
              const float* __restrict__ Wv,
              float* __restrict__ Qp, float* __restrict__ Kp,
              float* __restrict__ Vp) {
    const int z = blockIdx.z;
    const float* Bg = (z == 0) ? Wq : (z == 1) ? Wk : Wv;
    float*       Cg = (z == 0) ? Qp : (z == 1) ? Kp : Vp;
    gemm_body<1>(q, Bg, Cg);
}

__global__ __launch_bounds__(128, 2)
void out_gemm(const float* __restrict__ Ag, const float* __restrict__ Bg,
              float* __restrict__ Cg) {
    gemm_body<0>(Ag, Bg, Cg);
}

// ---------------------------------------------------------------------------
// RoPE (interleaved pairs), in place on Q and K (head-major layout).
// ---------------------------------------------------------------------------
__global__ void rope_kernel(float* __restrict__ Q, float* __restrict__ K) {
    int idx = blockIdx.x * blockDim.x + threadIdx.x;
    int i = idx & 63;
    int npos = (idx >> 6) & 2047;
    float freq = __powf(10000.0f, -(float)i * (1.0f / 63.0f));
    float th = (float)npos * freq;
    float s, c;
    sincosf(th, &s, &c);
    size_t base = (size_t)idx * 2;

    float q0 = Q[base], q1 = Q[base + 1];
    Q[base]     = q0 * c - q1 * s;
    Q[base + 1] = q1 * c + q0 * s;

    float k0 = K[base], k1 = K[base + 1];
    K[base]     = k0 * c - k1 * s;
    K[base + 1] = k1 * c + k0 * s;
}

// ---------------------------------------------------------------------------
// Tensor-core causal flash attention v4.
// v3 + register pipelining: K-frags double-buffered across kd; PV A-frags
// (shuffle+rna) hoisted ahead of the MMA loop.
// ---------------------------------------------------------------------------
constexpr int AQT = 64;
constexpr int AKT = 32;
constexpr int K_TILE_B  = AKT * 128 * 4;          // 16384 B
constexpr int STAGE_F   = AKT * 128 * 2;          // 8192 floats (K + V)
constexpr int ATTN_SMEM = 2 * STAGE_F * 4;        // 65536 B

__global__ __launch_bounds__(128)
void attn_mma_kernel(const float* __restrict__ Q, const float* __restrict__ K,
                     const float* __restrict__ V, float* __restrict__ O) {
    extern __shared__ float smx[];
    const uint32_t sbase = smem_u32(smx);

    const int tid  = threadIdx.x;
    const int lane = tid & 31;
    const int wid  = tid >> 5;          // 0..3
    const int gid  = lane >> 2, tig = lane & 3;
    const int bh   = blockIdx.y;
    const int qt   = gridDim.x - 1 - blockIdx.x;   // heavy tiles first
    const int q0   = qt * AQT;

    const float* Qb = Q + (size_t)bh * N * A;
    const float* Kb = K + (size_t)bh * N * A;
    const float* Vb = V + (size_t)bh * N * A;

    // ---- stage Q (64 rows x 512B) row-major swizzled into stage-0 alias ----
    {
        const int c16 = tid & 31;
        const int r0  = tid >> 5;       // 0..3
#pragma unroll
        for (int i = 0; i < 16; i++) {
            int row = r0 + i * 4;
            uint32_t off = (uint32_t)row * 512 + ((c16 ^ (row & 7)) << 4);
            CP_ASYNC16(sbase + off, Qb + (size_t)(q0 + row) * A + c16 * 4);
        }
        CP_COMMIT();
        CP_WAIT(0);
        __syncthreads();
    }

    // ---- Q A-frags -> registers; fold 1/sqrt(128) * log2(e) into scale ----
    const float scl = 0.08838834764831845f * 1.4426950408889634f;
    uint32_t qf[16][4];
    {
        const int a_row = wid * 16 + (lane & 15);
        const int a_hi  = lane >> 4;
#pragma unroll
        for (int kd = 0; kd < 16; kd++) {
            uint32_t addr = sbase + (uint32_t)a_row * 512
                          + (((kd * 2 + a_hi) ^ (a_row & 7)) << 4);
            ldsm_x4(qf[kd], addr);
#pragma unroll
            for (int j = 0; j < 4; j++)
                qf[kd][j] = rna_tf32_bits(__uint_as_float(qf[kd][j]) * scl);
        }
    }
    __syncthreads();   // Q smem now reusable as KV stage 0

    // ---- KV staging ----
    const int s_c16 = tid & 31;
    const int s_r0  = tid >> 5;
    // V layout: [kf][lane][chunk^(lane&7)][pos]
    const int v_d7  = (tid & 7) * 4;
    const int v_pos = ((tid >> 3) & 1) * 2;
    const int v_chk = tid >> 4;
    auto stage = [&](int kt, int slot) {
        const uint32_t kb = sbase + slot * (STAGE_F * 4);
        const uint32_t vb = kb + K_TILE_B;
        const float* Kg = Kb + (size_t)(kt * AKT) * A;
        const float* Vg = Vb + (size_t)(kt * AKT) * A + tid;
#pragma unroll
        for (int i = 0; i < 8; i++) {
            int row = s_r0 + i * 4;
            uint32_t off = (uint32_t)row * 512 + ((s_c16 ^ (row & 7)) << 4);
            CP_ASYNC16(kb + off, Kg + (size_t)row * A + s_c16 * 4);
        }
#pragma unroll
        for (int key = 0; key < 32; key++) {
            int kf    = key >> 3;
            int lanev = v_d7 + (key & 3);
            int chunk = v_chk ^ (lanev & 7);
            int pos   = v_pos + ((key >> 2) & 1);
            uint32_t va = vb + ((((kf * 32 + lanev) * 32) + chunk * 4 + pos) << 2);
            CP_ASYNC4(va, Vg + (size_t)key * A);
        }
    };

    const int nkt  = 2 * qt + 2;
    const int nktw = 2 * qt + (wid >> 1) + 1;

    float o[16][4];
#pragma unroll
    for (int nf = 0; nf < 16; nf++)
#pragma unroll
        for (int j = 0; j < 4; j++) o[nf][j] = 0.f;
    float m0 = -1e30f, m1 = -1e30f, l0 = 0.f, l1 = 0.f;

    const int row0 = q0 + wid * 16 + gid;
    const int row1 = row0 + 8;
    const int b_row = (lane & 7) + ((lane >> 4) << 3);   // 0..15
    const int b_hi  = (lane >> 3) & 1;

    stage(0, 0); CP_COMMIT();
    stage(1, 1); CP_COMMIT();

    for (int kt = 0; kt < nkt; kt++) {
        const int buf = kt & 1;
        if (kt < nkt - 1) { CP_WAIT(1); } else { CP_WAIT(0); }
        __syncthreads();

        if (kt < nktw) {
            const uint32_t kbase = sbase + buf * (STAGE_F * 4);
            const float*   vbuf  = smx + buf * STAGE_F + AKT * 128;

            // ---- S = Q K^T : split accumulators + pipelined K frags ----
            float s2[2][4][4];
#pragma unroll
            for (int p = 0; p < 2; p++)
#pragma unroll
                for (int nk = 0; nk < 4; nk++)
#pragma unroll
                    for (int j = 0; j < 4; j++) s2[p][nk][j] = 0.f;

            uint32_t kf0[2][4], kf1[2][4];
            auto load_k = [&](int bufr, int kd) {
                uint32_t col = ((kd * 2 + b_hi) ^ (b_row & 7)) << 4;
                ldsm_x4(kf0[bufr], kbase + (uint32_t)b_row * 512 + col);
                ldsm_x4(kf1[bufr], kbase + (uint32_t)(b_row + 16) * 512 + col);
            };

            load_k(0, 0);
#pragma unroll
            for (int kd = 0; kd < 16; kd++) {
                const int cur = kd & 1;
                if (kd < 15) load_k(cur ^ 1, kd + 1);
                float* sp = &s2[cur][0][0];
                mma_tf32(sp + 0,  qf[kd], kf0[cur][0], kf0[cur][1]);
                mma_tf32(sp + 4,  qf[kd], kf0[cur][2], kf0[cur][3]);
                mma_tf32(sp + 8,  qf[kd], kf1[cur][0], kf1[cur][1]);
                mma_tf32(sp + 12, qf[kd], kf1[cur][2], kf1[cur][3]);
            }
            float s[4][4];
#pragma unroll
            for (int nk = 0; nk < 4; nk++)
#pragma unroll
                for (int j = 0; j < 4; j++)
                    s[nk][j] = s2[0][nk][j] + s2[1][nk][j];

            // ---- causal mask (diagonal tile only) ----
            if (kt == nktw - 1) {
                int colb = kt * AKT + 2 * tig;
#pragma unroll
                for (int nk = 0; nk < 4; nk++) {
                    int c0 = colb + nk * 8;
                    if (c0     > row0) s[nk][0] = -1e30f;
                    if (c0 + 1 > row0) s[nk][1] = -1e30f;
                    if (c0     > row1) s[nk][2] = -1e30f;
                    if (c0 + 1 > row1) s[nk][3] = -1e30f;
                }
            }

            // ---- online softmax (log2 domain) ----
            float mx0 = -1e30f, mx1 = -1e30f;
#pragma unroll
            for (int nk = 0; nk < 4; nk++) {
                mx0 = fmaxf(mx0, fmaxf(s[nk][0], s[nk][1]));
                mx1 = fmaxf(mx1, fmaxf(s[nk][2], s[nk][3]));
            }
            mx0 = fmaxf(mx0, __shfl_xor_sync(0xffffffffu, mx0, 1));
            mx0 = fmaxf(mx0, __shfl_xor_sync(0xffffffffu, mx0, 2));
            mx1 = fmaxf(mx1, __shfl_xor_sync(0xffffffffu, mx1, 1));
            mx1 = fmaxf(mx1, __shfl_xor_sync(0xffffffffu, mx1, 2));
            float mn0 = fmaxf(m0, mx0), mn1 = fmaxf(m1, mx1);
            float cor0 = ex2f(m0 - mn0), cor1 = ex2f(m1 - mn1);
            m0 = mn0; m1 = mn1;

            float rs0 = 0.f, rs1 = 0.f;
#pragma unroll
            for (int nk = 0; nk < 4; nk++) {
                s[nk][0] = ex2f(s[nk][0] - mn0);
                s[nk][1] = ex2f(s[nk][1] - mn0);
                s[nk][2] = ex2f(s[nk][2] - mn1);
                s[nk][3] = ex2f(s[nk][3] - mn1);
                rs0 += s[nk][0] + s[nk][1];
                rs1 += s[nk][2] + s[nk][3];
            }
            rs0 += __shfl_xor_sync(0xffffffffu, rs0, 1);
            rs0 += __shfl_xor_sync(0xffffffffu, rs0, 2);
            rs1 += __shfl_xor_sync(0xffffffffu, rs1, 1);
            rs1 += __shfl_xor_sync(0xffffffffu, rs1, 2);
            l0 = l0 * cor0 + rs0;
            l1 = l1 * cor1 + rs1;

#pragma unroll
            for (int nf = 0; nf < 16; nf++) {
                o[nf][0] *= cor0; o[nf][1] *= cor0;
                o[nf][2] *= cor1; o[nf][3] *= cor1;
            }

            // ---- precompute ALL P A-frags (shuffles + rna hoisted) ----
            const int lA = (gid << 2) + (tig >> 1);
            const int lB = lA + 2;
            const bool odd = tig & 1;
            uint32_t aP[4][4];
#pragma unroll
            for (int kf = 0; kf < 4; kf++) {
                float p0 = s[kf][0], p1 = s[kf][1], p2 = s[kf][2], p3 = s[kf][3];
                float x0 = __shfl_sync(0xffffffffu, p0, lA);
                float x1 = __shfl_sync(0xffffffffu, p1, lA);
                float y0 = __shfl_sync(0xffffffffu, p0, lB);
                float y1 = __shfl_sync(0xffffffffu, p1, lB);
                float z0 = __shfl_sync(0xffffffffu, p2, lA);
                float z1 = __shfl_sync(0xffffffffu, p3, lA);
                float w0 = __shfl_sync(0xffffffffu, p2, lB);
                float w1 = __shfl_sync(0xffffffffu, p3, lB);
                aP[kf][0] = rna_tf32_bits(odd ? x1 : x0);
                aP[kf][1] = rna_tf32_bits(odd ? z1 : z0);
                aP[kf][2] = rna_tf32_bits(odd ? y1 : y0);
                aP[kf][3] = rna_tf32_bits(odd ? w1 : w0);
            }

            // ---- O += P V (pure lds.128 + MMA loop) ----
            const float* vrow = vbuf + (uint32_t)lane * 32;
            const int ln7 = (lane & 7);
#pragma unroll
            for (int kf = 0; kf < 4; kf++) {
                const float* vk = vrow + kf * 32 * 32;
#pragma unroll
                for (int j2 = 0; j2 < 8; j2++) {
                    float4 vv = *(const float4*)(vk + ((j2 ^ ln7) << 2));
                    mma_tf32(o[2 * j2],     aP[kf], __float_as_uint(vv.x),
                                                    __float_as_uint(vv.y));
                    mma_tf32(o[2 * j2 + 1], aP[kf], __float_as_uint(vv.z),
                                                    __float_as_uint(vv.w));
                }
            }
        }

        __syncthreads();
        if (kt + 2 < nkt) { stage(kt + 2, buf); CP_COMMIT(); }
    }

    // ---- write output: [b*n, h*a], rna for Wo GEMM ----
    const float il0 = 1.f / l0, il1 = 1.f / l1;
    const int b2 = bh >> 4, h2 = bh & 15;
    float* o0 = O + (size_t)(b2 * N + row0) * HD + h2 * A;
    float* o1 = O + (size_t)(b2 * N + row1) * HD + h2 * A;
#pragma unroll
    for (int nf = 0; nf < 16; nf++) {
        int col = nf * 8 + 2 * tig;
        *(float2*)(o0 + col) = make_float2(rna_tf32(o[nf][0] * il0),
                                           rna_tf32(o[nf][1] * il0));
        *(float2*)(o1 + col) = make_float2(rna_tf32(o[nf][2] * il1),
                                           rna_tf32(o[nf][3] * il1));
    }
}

// ---------------------------------------------------------------------------
extern "C" void kernel_launch(void* const* d_in, const int* in_sizes, int n_in,
                              void* d_out, int out_size) {
    const float* q  = (const float*)d_in[0];
    const float* Wq = (const float*)d_in[1];
    const float* Wk = (const float*)d_in[2];
    const float* Wv = (const float*)d_in[3];
    const float* Wo = (const float*)d_in[4];
    float* out = (float*)d_out;

    float *qr, *Wqr, *Wkr, *Wvr, *Wor, *Qp, *Kp, *Vp, *AOp;
    cudaGetSymbolAddress((void**)&qr,  g_qr);
    cudaGetSymbolAddress((void**)&Wqr, g_Wqr);
    cudaGetSymbolAddress((void**)&Wkr, g_Wkr);
    cudaGetSymbolAddress((void**)&Wvr, g_Wvr);
    cudaGetSymbolAddress((void**)&Wor, g_Wor);
    cudaGetSymbolAddress((void**)&Qp,  g_Q);
    cudaGetSymbolAddress((void**)&Kp,  g_K);
    cudaGetSymbolAddress((void**)&Vp,  g_V);
    cudaGetSymbolAddress((void**)&AOp, g_AO);

    cudaFuncSetAttribute(qkv_gemm, cudaFuncAttributeMaxDynamicSharedMemorySize,
                         GEMM_SMEM);
    cudaFuncSetAttribute(out_gemm, cudaFuncAttributeMaxDynamicSharedMemorySize,
                         GEMM_SMEM);
    cudaFuncSetAttribute(attn_mma_kernel,
                         cudaFuncAttributeMaxDynamicSharedMemorySize, ATTN_SMEM);

    // fused rna pre-pass (q + 4 weights)
    {
        int total = NQ4 + 4 * NW4;   // 6,291,456
        round_all_kernel<<<total / 256, 256>>>(
            (const float4*)q, (const float4*)Wq, (const float4*)Wk,
            (const float4*)Wv, (const float4*)Wo,
            (float4*)qr, (float4*)Wqr, (float4*)Wkr, (float4*)Wvr, (float4*)Wor);
    }

    // fused QKV projections (64x64 warp tiles, frag-pipelined)
    qkv_gemm<<<dim3(16, 32, 3), 128, GEMM_SMEM>>>(qr, Wqr, Wkr, Wvr, Qp, Kp, Vp);

    // RoPE on Q and K
    int npairs = B * H * N * (A / 2);
    rope_kernel<<<npairs / 256, 256>>>(Qp, Kp);

    // tensor-core causal flash attention
    attn_mma_kernel<<<dim3(N / AQT, B * H), 128, ATTN_SMEM>>>(Qp, Kp, Vp, AOp);

    // output projection
    out_gemm<<<dim3(16, 32), 128, GEMM_SMEM>>>(AOp, Wor, out);
}

// round 10
// speedup vs baseline: 1.0363x; 1.0363x over previous
#include <cuda_runtime.h>
#include <cstdint>
#include <math.h>

// Problem constants
constexpr int B = 2;
constexpr int H = 16;
constexpr int N = 2048;
constexpr int A = 128;           // head dim
constexpr int W = 2048;          // model width
constexpr int HD = H * A;        // 2048
constexpr int Mdim = B * N;      // 4096
constexpr int Kdim = W;          // 2048

// Scratch (device globals — no allocation allowed)
__device__ float g_qr [Mdim * Kdim];     // tf32-rounded q
__device__ float g_Wqr[HD * W];
__device__ float g_Wkr[HD * W];
__device__ float g_Wvr[HD * W];
__device__ float g_Wor[W * HD];
__device__ float g_Q  [B * H * N * A];   // head-major (rope applied)
__device__ float g_K  [B * H * N * A];
__device__ float g_V  [B * H * N * A];
__device__ float g_AO [Mdim * HD];       // [b*n, h*a], rna-rounded by attention
__device__ float2 g_rope[N * 64];        // (sin, cos) per (n, pair)

// ---------------------------------------------------------------------------
// helpers
// ---------------------------------------------------------------------------
__device__ __forceinline__ float rna_tf32(float x) {
    uint32_t u;
    asm("cvt.rna.tf32.f32 %0, %1;" : "=r"(u) : "f"(x));
    return __uint_as_float(u);
}
__device__ __forceinline__ uint32_t rna_tf32_bits(float x) {
    uint32_t u;
    asm("cvt.rna.tf32.f32 %0, %1;" : "=r"(u) : "f"(x));
    return u;
}
__device__ __forceinline__ float ex2f(float x) {
    float y;
    asm("ex2.approx.ftz.f32 %0, %1;" : "=f"(y) : "f"(x));
    return y;
}
__device__ __forceinline__ uint32_t smem_u32(const void* p) {
    uint32_t a;
    asm("{ .reg .u64 t; cvta.to.shared.u64 t, %1; cvt.u32.u64 %0, t; }"
        : "=r"(a) : "l"(p));
    return a;
}
__device__ __forceinline__ void mma_tf32(float* c, const uint32_t* a,
                                         uint32_t b0, uint32_t b1) {
    asm volatile(
        "mma.sync.aligned.m16n8k8.row.col.f32.tf32.tf32.f32 "
        "{%0,%1,%2,%3}, {%4,%5,%6,%7}, {%8,%9}, {%0,%1,%2,%3};"
        : "+f"(c[0]), "+f"(c[1]), "+f"(c[2]), "+f"(c[3])
        : "r"(a[0]), "r"(a[1]), "r"(a[2]), "r"(a[3]), "r"(b0), "r"(b1));
}
__device__ __forceinline__ void ldsm_x4(uint32_t* r, uint32_t addr) {
    asm volatile("ldmatrix.sync.aligned.m8n8.x4.shared.b16 {%0,%1,%2,%3}, [%4];"
                 : "=r"(r[0]), "=r"(r[1]), "=r"(r[2]), "=r"(r[3]) : "r"(addr));
}
#define CP_ASYNC4(dst, src) \
    asm volatile("cp.async.ca.shared.global [%0], [%1], 4;" :: "r"(dst), "l"(src))
#define CP_ASYNC16(dst, src) \
    asm volatile("cp.async.cg.shared.global [%0], [%1], 16;" :: "r"(dst), "l"(src))
#define CP_COMMIT() asm volatile("cp.async.commit_group;" ::: "memory")
#define CP_WAIT(n)  asm volatile("cp.async.wait_group %0;" :: "n"(n) : "memory")

// ---------------------------------------------------------------------------
// rope sin/cos table: theta[n, i] = n * 10000^{-i/63}
// ---------------------------------------------------------------------------
__global__ void rope_table_kernel() {
    int idx = blockIdx.x * blockDim.x + threadIdx.x;   // [0, 2048*64)
    int i = idx & 63, n = idx >> 6;
    float freq = __powf(10000.0f, -(float)i * (1.0f / 63.0f));
    float s, c;
    sincosf((float)n * freq, &s, &c);
    g_rope[idx] = make_float2(s, c);
}

// ---------------------------------------------------------------------------
// Fused rna-rounding pre-pass over q + 4 weights (single DRAM-bound launch).
// ---------------------------------------------------------------------------
constexpr int NQ4 = Mdim * Kdim / 4;   // 2,097,152
constexpr int NW4 = HD * W / 4;        // 1,048,576 = 2^20

__global__ void round_all_kernel(const float4* __restrict__ q,
                                 const float4* __restrict__ wq,
                                 const float4* __restrict__ wk,
                                 const float4* __restrict__ wv,
                                 const float4* __restrict__ wo,
                                 float4* __restrict__ qr,
                                 float4* __restrict__ wqr,
                                 float4* __restrict__ wkr,
                                 float4* __restrict__ wvr,
                                 float4* __restrict__ wor) {
    int i = blockIdx.x * blockDim.x + threadIdx.x;
    const float4* src;
    float4* dst;
    int off;
    if (i < NQ4) {
        src = q; dst = qr; off = i;
    } else {
        int j = i - NQ4;
        int w = j >> 20;
        off = j & (NW4 - 1);
        src = (w == 0) ? wq : (w == 1) ? wk : (w == 2) ? wv : wo;
        dst = (w == 0) ? wqr : (w == 1) ? wkr : (w == 2) ? wvr : wor;
    }
    float4 v = src[off];
    v.x = rna_tf32(v.x); v.y = rna_tf32(v.y);
    v.z = rna_tf32(v.z); v.w = rna_tf32(v.w);
    dst[off] = v;
}

// ---------------------------------------------------------------------------
// tf32 mma.sync GEMM: 128x128 CTA, BK=32, 128 threads, 4 warps of 64x64.
// 3-stage cp.async pipeline, XOR-swizzled row-major smem, ldmatrix.x4.
// Optional fused RoPE in the epilogue (Q/K projections).
// ---------------------------------------------------------------------------
constexpr int TILE_B     = 128 * 32 * 4;          // 16384 per operand
constexpr int STAGE_B    = 2 * TILE_B;            // 32768
constexpr int GEMM_SMEM  = 3 * STAGE_B;           // 98304

template <int SCATTER_C>
__device__ __forceinline__ void gemm_body(const float* __restrict__ Ag,
                                          const float* __restrict__ Bg,
                                          float* __restrict__ Cg,
                                          bool doRope) {
    extern __shared__ float gs[];
    const uint32_t sbase = smem_u32(gs);
    const int tid  = threadIdx.x;
    const int lane = tid & 31;
    const int wid  = tid >> 5;      // 0..3
    const int wm   = wid & 1;       // 64 rows each
    const int wn   = wid >> 1;      // 64 cols each
    const int m0   = blockIdx.y * 128;
    const int n0   = blockIdx.x * 128;

    float c[4][8][4];
#pragma unroll
    for (int mi = 0; mi < 4; mi++)
#pragma unroll
        for (int ni = 0; ni < 8; ni++)
#pragma unroll
            for (int j = 0; j < 4; j++) c[mi][ni][j] = 0.f;

    const int srow0 = tid >> 3;     // 0..15
    const int sc16  = tid & 7;
    auto stage = [&](int kt, int slot) {
        const uint32_t base = sbase + slot * STAGE_B;
        const float* Asrc = Ag + (size_t)(m0 + srow0) * Kdim + kt * 32 + sc16 * 4;
        const float* Bsrc = Bg + (size_t)(n0 + srow0) * Kdim + kt * 32 + sc16 * 4;
#pragma unroll
        for (int i = 0; i < 8; i++) {
            int row = srow0 + i * 16;
            uint32_t off = (uint32_t)row * 128 + ((sc16 ^ (row & 7)) << 4);
            CP_ASYNC16(base + off,          Asrc + (size_t)i * 16 * Kdim);
            CP_ASYNC16(base + TILE_B + off, Bsrc + (size_t)i * 16 * Kdim);
        }
    };

    const int a_row = wm * 64 + (lane & 15);
    const int a_hi  = lane >> 4;
    const int b_row = wn * 64 + (lane & 7) + ((lane >> 4) << 3);
    const int b_hi  = (lane >> 3) & 1;

    stage(0, 0); CP_COMMIT();
    stage(1, 1); CP_COMMIT();

    constexpr int NKT = Kdim / 32;
    int slot = 0;
    for (int kt = 0; kt < NKT; kt++) {
        CP_WAIT(1);
        __syncthreads();
        if (kt + 2 < NKT) {
            int ns = slot + 2; if (ns >= 3) ns -= 3;
            stage(kt + 2, ns);
        }
        CP_COMMIT();

        const uint32_t abase = sbase + slot * STAGE_B;
        const uint32_t bbase = abase + TILE_B;
#pragma unroll
        for (int ks = 0; ks < 4; ks++) {
            uint32_t af[4][4];
#pragma unroll
            for (int mi = 0; mi < 4; mi++) {
                int row = a_row + mi * 16;
                uint32_t addr = abase + (uint32_t)row * 128
                              + (((ks * 2 + a_hi) ^ (row & 7)) << 4);
                ldsm_x4(af[mi], addr);
            }
#pragma unroll
            for (int nip = 0; nip < 4; nip++) {
                int row = b_row + nip * 16;
                uint32_t addr = bbase + (uint32_t)row * 128
                              + (((ks * 2 + b_hi) ^ (row & 7)) << 4);
                uint32_t bf[4];
                ldsm_x4(bf, addr);
#pragma unroll
                for (int mi = 0; mi < 4; mi++) {
                    mma_tf32(c[mi][2 * nip],     af[mi], bf[0], bf[1]);
                    mma_tf32(c[mi][2 * nip + 1], af[mi], bf[2], bf[3]);
                }
            }
        }
        slot++; if (slot >= 3) slot = 0;
    }

    const int gid = lane >> 2, tig = lane & 3;
#pragma unroll
    for (int mi = 0; mi < 4; mi++) {
#pragma unroll
        for (int ni = 0; ni < 8; ni++) {
            int n = n0 + wn * 64 + ni * 8 + tig * 2;
#pragma unroll
            for (int half = 0; half < 2; half++) {
                int m = m0 + wm * 64 + mi * 16 + gid + half * 8;
                float2 v = make_float2(c[mi][ni][half * 2], c[mi][ni][half * 2 + 1]);
                if (doRope) {
                    int pi   = (n & 127) >> 1;
                    int npos = m & 2047;
                    float2 sc = g_rope[(npos << 6) + pi];
                    float ev = v.x * sc.y - v.y * sc.x;
                    float ov = v.y * sc.y + v.x * sc.x;
                    v = make_float2(ev, ov);
                }
                size_t dst;
                if (SCATTER_C) {
                    int b2 = m >> 11, np = m & 2047, h2 = n >> 7, a0 = n & 127;
                    dst = ((((size_t)b2 * H + h2) * N) + np) * A + a0;
                } else {
                    dst = (size_t)m * 2048 + n;
                }
                *(float2*)(Cg + dst) = v;
            }
        }
    }
}

__global__ __launch_bounds__(128, 2)
void qkv_gemm(const float* __restrict__ q,
              const float* __restrict__ Wq, const float* __restrict__ Wk,
              const float* __restrict__ Wv,
              float* __restrict__ Qp, float* __restrict__ Kp,
              float* __restrict__ Vp) {
    const int z = blockIdx.z;
    const float* Bg = (z == 0) ? Wq : (z == 1) ? Wk : Wv;
    float*       Cg = (z == 0) ? Qp : (z == 1) ? Kp : Vp;
    gemm_body<1>(q, Bg, Cg, z < 2);
}

__global__ __launch_bounds__(128, 2)
void out_gemm(const float* __restrict__ Ag, const float* __restrict__ Bg,
              float* __restrict__ Cg) {
    gemm_body<0>(Ag, Bg, Cg, false);
}

// ---------------------------------------------------------------------------
// Tensor-core causal flash attention v5.
// v4 + permuted-K smem layout: S C-fragments ARE the P A-fragments (register
// rename {0,2,1,3}) — the PV shuffle-transpose is eliminated entirely.
// Keys within each 8-group stored at row ((k&3)<<1)|((k>>2)&1).
// ---------------------------------------------------------------------------
constexpr int AQT = 64;
constexpr int AKT = 32;
constexpr int K_TILE_B  = AKT * 128 * 4;          // 16384 B
constexpr int STAGE_F   = AKT * 128 * 2;          // 8192 floats (K + V)
constexpr int ATTN_SMEM = 2 * STAGE_F * 4;        // 65536 B

__global__ __launch_bounds__(128)
void attn_mma_kernel(const float* __restrict__ Q, const float* __restrict__ K,
                     const float* __restrict__ V, float* __restrict__ O) {
    extern __shared__ float smx[];
    const uint32_t sbase = smem_u32(smx);

    const int tid  = threadIdx.x;
    const int lane = tid & 31;
    const int wid  = tid >> 5;          // 0..3
    const int gid  = lane >> 2, tig = lane & 3;
    const int bh   = blockIdx.y;
    const int qt   = gridDim.x - 1 - blockIdx.x;   // heavy tiles first
    const int q0   = qt * AQT;

    const float* Qb = Q + (size_t)bh * N * A;
    const float* Kb = K + (size_t)bh * N * A;
    const float* Vb = V + (size_t)bh * N * A;

    // ---- stage Q (64 rows x 512B) row-major swizzled into stage-0 alias ----
    {
        const int c16 = tid & 31;
        const int r0  = tid >> 5;       // 0..3
#pragma unroll
        for (int i = 0; i < 16; i++) {
            int row = r0 + i * 4;
            uint32_t off = (uint32_t)row * 512 + ((c16 ^ (row & 7)) << 4);
            CP_ASYNC16(sbase + off, Qb + (size_t)(q0 + row) * A + c16 * 4);
        }
        CP_COMMIT();
        CP_WAIT(0);
        __syncthreads();
    }

    // ---- Q A-frags -> registers; fold 1/sqrt(128) * log2(e) into scale ----
    const float scl = 0.08838834764831845f * 1.4426950408889634f;
    uint32_t qf[16][4];
    {
        const int a_row = wid * 16 + (lane & 15);
        const int a_hi  = lane >> 4;
#pragma unroll
        for (int kd = 0; kd < 16; kd++) {
            uint32_t addr = sbase + (uint32_t)a_row * 512
                          + (((kd * 2 + a_hi) ^ (a_row & 7)) << 4);
            ldsm_x4(qf[kd], addr);
#pragma unroll
            for (int j = 0; j < 4; j++)
                qf[kd][j] = rna_tf32_bits(__uint_as_float(qf[kd][j]) * scl);
        }
    }
    __syncthreads();   // Q smem now reusable as KV stage 0

    // ---- KV staging (K rows permuted within 8-groups) ----
    const int s_c16 = tid & 31;
    const int s_r0  = tid >> 5;
    const int v_d7  = (tid & 7) * 4;
    const int v_pos = ((tid >> 3) & 1) * 2;
    const int v_chk = tid >> 4;
    auto stage = [&](int kt, int slot) {
        const uint32_t kb = sbase + slot * (STAGE_F * 4);
        const uint32_t vb = kb + K_TILE_B;
        const float* Kg = Kb + (size_t)(kt * AKT) * A;
        const float* Vg = Vb + (size_t)(kt * AKT) * A + tid;
#pragma unroll
        for (int i = 0; i < 8; i++) {
            int row  = s_r0 + i * 4;   // key index
            int prow = (row & ~7) | ((row & 3) << 1) | ((row >> 2) & 1);
            uint32_t off = (uint32_t)prow * 512 + ((s_c16 ^ (prow & 7)) << 4);
            CP_ASYNC16(kb + off, Kg + (size_t)row * A + s_c16 * 4);
        }
#pragma unroll
        for (int key = 0; key < 32; key++) {
            int kf    = key >> 3;
            int lanev = v_d7 + (key & 3);
            int chunk = v_chk ^ (lanev & 7);
            int pos   = v_pos + ((key >> 2) & 1);
            uint32_t va = vb + ((((kf * 32 + lanev) * 32) + chunk * 4 + pos) << 2);
            CP_ASYNC4(va, Vg + (size_t)key * A);
        }
    };

    const int nkt  = 2 * qt + 2;
    const int nktw = 2 * qt + (wid >> 1) + 1;

    float o[16][4];
#pragma unroll
    for (int nf = 0; nf < 16; nf++)
#pragma unroll
        for (int j = 0; j < 4; j++) o[nf][j] = 0.f;
    float m0 = -1e30f, m1 = -1e30f, l0 = 0.f, l1 = 0.f;

    const int row0 = q0 + wid * 16 + gid;
    const int row1 = row0 + 8;
    const int b_row = (lane & 7) + ((lane >> 4) << 3);   // 0..15
    const int b_hi  = (lane >> 3) & 1;

    stage(0, 0); CP_COMMIT();
    stage(1, 1); CP_COMMIT();

    for (int kt = 0; kt < nkt; kt++) {
        const int buf = kt & 1;
        if (kt < nkt - 1) { CP_WAIT(1); } else { CP_WAIT(0); }
        __syncthreads();

        if (kt < nktw) {
            const uint32_t kbase = sbase + buf * (STAGE_F * 4);
            const float*   vbuf  = smx + buf * STAGE_F + AKT * 128;

            // ---- S = Q K^T : split accumulators + pipelined K frags ----
            float s2[2][4][4];
#pragma unroll
            for (int p = 0; p < 2; p++)
#pragma unroll
                for (int nk = 0; nk < 4; nk++)
#pragma unroll
                    for (int j = 0; j < 4; j++) s2[p][nk][j] = 0.f;

            uint32_t kfA[2][4], kfB[2][4];
            auto load_k = [&](int bufr, int kd) {
                uint32_t col = ((kd * 2 + b_hi) ^ (b_row & 7)) << 4;
                ldsm_x4(kfA[bufr], kbase + (uint32_t)b_row * 512 + col);
                ldsm_x4(kfB[bufr], kbase + (uint32_t)(b_row + 16) * 512 + col);
            };

            load_k(0, 0);
#pragma unroll
            for (int kd = 0; kd < 16; kd++) {
                const int cur = kd & 1;
                if (kd < 15) load_k(cur ^ 1, kd + 1);
                float* sp = &s2[cur][0][0];
                mma_tf32(sp + 0,  qf[kd], kfA[cur][0], kfA[cur][1]);
                mma_tf32(sp + 4,  qf[kd], kfA[cur][2], kfA[cur][3]);
                mma_tf32(sp + 8,  qf[kd], kfB[cur][0], kfB[cur][1]);
                mma_tf32(sp + 12, qf[kd], kfB[cur][2], kfB[cur][3]);
            }
            float s[4][4];
#pragma unroll
            for (int nk = 0; nk < 4; nk++)
#pragma unroll
                for (int j = 0; j < 4; j++)
                    s[nk][j] = s2[0][nk][j] + s2[1][nk][j];

            // ---- causal mask (diagonal tile only; permuted columns) ----
            // s[nk][0]: (row0, kb+tig)   s[nk][1]: (row0, kb+tig+4)
            // s[nk][2]: (row1, kb+tig)   s[nk][3]: (row1, kb+tig+4)
            if (kt == nktw - 1) {
                int colb = kt * AKT + tig;
#pragma unroll
                for (int nk = 0; nk < 4; nk++) {
                    int c0 = colb + nk * 8;
                    if (c0     > row0) s[nk][0] = -1e30f;
                    if (c0 + 4 > row0) s[nk][1] = -1e30f;
                    if (c0     > row1) s[nk][2] = -1e30f;
                    if (c0 + 4 > row1) s[nk][3] = -1e30f;
                }
            }

            // ---- online softmax (log2 domain) ----
            float mx0 = -1e30f, mx1 = -1e30f;
#pragma unroll
            for (int nk = 0; nk < 4; nk++) {
                mx0 = fmaxf(mx0, fmaxf(s[nk][0], s[nk][1]));
                mx1 = fmaxf(mx1, fmaxf(s[nk][2], s[nk][3]));
            }
            mx0 = fmaxf(mx0, __shfl_xor_sync(0xffffffffu, mx0, 1));
            mx0 = fmaxf(mx0, __shfl_xor_sync(0xffffffffu, mx0, 2));
            mx1 = fmaxf(mx1, __shfl_xor_sync(0xffffffffu, mx1, 1));
            mx1 = fmaxf(mx1, __shfl_xor_sync(0xffffffffu, mx1, 2));
            float mn0 = fmaxf(m0, mx0), mn1 = fmaxf(m1, mx1);
            float cor0 = ex2f(m0 - mn0), cor1 = ex2f(m1 - mn1);
            m0 = mn0; m1 = mn1;

            float rs0 = 0.f, rs1 = 0.f;
#pragma unroll
            for (int nk = 0; nk < 4; nk++) {
                s[nk][0] = ex2f(s[nk][0] - mn0);
                s[nk][1] = ex2f(s[nk][1] - mn0);
                s[nk][2] = ex2f(s[nk][2] - mn1);
                s[nk][3] = ex2f(s[nk][3] - mn1);
                rs0 += s[nk][0] + s[nk][1];
                rs1 += s[nk][2] + s[nk][3];
            }
            rs0 += __shfl_xor_sync(0xffffffffu, rs0, 1);
            rs0 += __shfl_xor_sync(0xffffffffu, rs0, 2);
            rs1 += __shfl_xor_sync(0xffffffffu, rs1, 1);
            rs1 += __shfl_xor_sync(0xffffffffu, rs1, 2);
            l0 = l0 * cor0 + rs0;
            l1 = l1 * cor1 + rs1;

#pragma unroll
            for (int nf = 0; nf < 16; nf++) {
                o[nf][0] *= cor0; o[nf][1] *= cor0;
                o[nf][2] *= cor1; o[nf][3] *= cor1;
            }

            // ---- P A-frags = register rename of S C-frags (no shuffles!) ----
            uint32_t aP[4][4];
#pragma unroll
            for (int kf = 0; kf < 4; kf++) {
                aP[kf][0] = rna_tf32_bits(s[kf][0]);
                aP[kf][1] = rna_tf32_bits(s[kf][2]);
                aP[kf][2] = rna_tf32_bits(s[kf][1]);
                aP[kf][3] = rna_tf32_bits(s[kf][3]);
            }

            // ---- O += P V (pure lds.128 + MMA loop) ----
            const float* vrow = vbuf + (uint32_t)lane * 32;
            const int ln7 = (lane & 7);
#pragma unroll
            for (int kf = 0; kf < 4; kf++) {
                const float* vk = vrow + kf * 32 * 32;
#pragma unroll
                for (int j2 = 0; j2 < 8; j2++) {
                    float4 vv = *(const float4*)(vk + ((j2 ^ ln7) << 2));
                    mma_tf32(o[2 * j2],     aP[kf], __float_as_uint(vv.x),
                                                    __float_as_uint(vv.y));
                    mma_tf32(o[2 * j2 + 1], aP[kf], __float_as_uint(vv.z),
                                                    __float_as_uint(vv.w));
                }
            }
        }

        __syncthreads();
        if (kt + 2 < nkt) { stage(kt + 2, buf); CP_COMMIT(); }
    }

    // ---- write output: [b*n, h*a], rna for Wo GEMM ----
    const float il0 = 1.f / l0, il1 = 1.f / l1;
    const int b2 = bh >> 4, h2 = bh & 15;
    float* o0 = O + (size_t)(b2 * N + row0) * HD + h2 * A;
    float* o1 = O + (size_t)(b2 * N + row1) * HD + h2 * A;
#pragma unroll
    for (int nf = 0; nf < 16; nf++) {
        int col = nf * 8 + 2 * tig;
        *(float2*)(o0 + col) = make_float2(rna_tf32(o[nf][0] * il0),
                                           rna_tf32(o[nf][1] * il0));
        *(float2*)(o1 + col) = make_float2(rna_tf32(o[nf][2] * il1),
                                           rna_tf32(o[nf][3] * il1));
    }
}

// ---------------------------------------------------------------------------
extern "C" void kernel_launch(void* const* d_in, const int* in_sizes, int n_in,
                              void* d_out, int out_size) {
    const float* q  = (const float*)d_in[0];
    const float* Wq = (const float*)d_in[1];
    const float* Wk = (const float*)d_in[2];
    const float* Wv = (const float*)d_in[3];
    const float* Wo = (const float*)d_in[4];
    float* out = (float*)d_out;

    float *qr, *Wqr, *Wkr, *Wvr, *Wor, *Qp, *Kp, *Vp, *AOp;
    cudaGetSymbolAddress((void**)&qr,  g_qr);
    cudaGetSymbolAddress((void**)&Wqr, g_Wqr);
    cudaGetSymbolAddress((void**)&Wkr, g_Wkr);
    cudaGetSymbolAddress((void**)&Wvr, g_Wvr);
    cudaGetSymbolAddress((void**)&Wor, g_Wor);
    cudaGetSymbolAddress((void**)&Qp,  g_Q);
    cudaGetSymbolAddress((void**)&Kp,  g_K);
    cudaGetSymbolAddress((void**)&Vp,  g_V);
    cudaGetSymbolAddress((void**)&AOp, g_AO);

    cudaFuncSetAttribute(qkv_gemm, cudaFuncAttributeMaxDynamicSharedMemorySize,
                         GEMM_SMEM);
    cudaFuncSetAttribute(out_gemm, cudaFuncAttributeMaxDynamicSharedMemorySize,
                         GEMM_SMEM);
    cudaFuncSetAttribute(attn_mma_kernel,
                         cudaFuncAttributeMaxDynamicSharedMemorySize, ATTN_SMEM);

    // rope sin/cos table + fused rna pre-pass (q + 4 weights)
    rope_table_kernel<<<(N * 64) / 256, 256>>>();
    {
        int total = NQ4 + 4 * NW4;   // 6,291,456
        round_all_kernel<<<total / 256, 256>>>(
            (const float4*)q, (const float4*)Wq, (const float4*)Wk,
            (const float4*)Wv, (const float4*)Wo,
            (float4*)qr, (float4*)Wqr, (float4*)Wkr, (float4*)Wvr, (float4*)Wor);
    }

    // fused QKV projections (rope applied in epilogue for Q/K)
    qkv_gemm<<<dim3(16, 32, 3), 128, GEMM_SMEM>>>(qr, Wqr, Wkr, Wvr, Qp, Kp, Vp);

    // tensor-core causal flash attention
    attn_mma_kernel<<<dim3(N / AQT, B * H), 128, ATTN_SMEM>>>(Qp, Kp, Vp, AOp);

    // output projection
    out_gemm<<<dim3(16, 32), 128, GEMM_SMEM>>>(AOp, Wor, out);
}